// round 9
// baseline (speedup 1.0000x reference)
#include <cuda_runtime.h>
#include <cstdint>

#define SEQ    2048
#define BATCH  16
#define HID    1024
#define M_TOT  (SEQ*BATCH)   /* 32768 */
#define N0     (3*HID)       /* 3072  */
#define N1     (2*HID)       /* 2048  */

#define BM 128
#define BN 128
#define BK 32
#define ASTR (BK + 4)        /* 36  */
#define BSTR (BN + 8)        /* 136 */
#define ASZ  (BM * ASTR)     /* 4608 words */
#define BSZ  (BK * BSTR)     /* 4352 words */
#define STAGE (ASZ + BSZ)    /* 8960 words = 35840 B */
#define NSTAGE 3
#define SMEM_BYTES (NSTAGE * STAGE * 4)  /* 107520 */

// Scratch (device globals: allocation APIs are forbidden)
__device__ float g_U    [(size_t)M_TOT * N0];   // U0 (ld=3072), then U1 (ld=2048)
__device__ float g_h1   [(size_t)M_TOT * HID];  // layer-1 output (tf32-rounded at store)
__device__ float g_hlast[BATCH * HID];          // exact (unrounded) h1 at t=SEQ-1
__device__ float g_xc   [(size_t)M_TOT * HID];  // x, tf32-rounded
__device__ float g_W0c  [(size_t)HID * N0];     // W0, tf32-rounded
__device__ float g_W1c  [(size_t)HID * N0];     // W1, tf32-rounded
__device__ float g_r2   [BATCH * HID];          // last-step r pre-activation, layer 2

__device__ __forceinline__ float f2tf32f(float f) {
    unsigned u;
    asm("cvt.rna.tf32.f32 %0, %1;" : "=r"(u) : "f"(f));
    return __uint_as_float(u);
}

__device__ __forceinline__ float sigm(float z) {
    return 1.0f / (1.0f + __expf(-z));
}

#define CP_ASYNC16(dst_u32, src_ptr) \
    asm volatile("cp.async.ca.shared.global [%0], [%1], 16;" :: "r"(dst_u32), "l"(src_ptr))

// Round an fp32 array to tf32 (bits in fp32 container). Pure streaming:
// bypass L2 retention on both sides (single-use data).
__global__ void tf32_round(const float4* __restrict__ src, float4* __restrict__ dst, int n4)
{
    for (int i = blockIdx.x * blockDim.x + threadIdx.x; i < n4; i += gridDim.x * blockDim.x) {
        float4 v = __ldcs(&src[i]);
        v.x = f2tf32f(v.x); v.y = f2tf32f(v.y);
        v.z = f2tf32f(v.z); v.w = f2tf32f(v.w);
        __stcs(&dst[i], v);
    }
}

// C[M x n] = A[M x 1024] @ B[1024 x n]; inputs pre-rounded to tf32.
// A row-major lda=1024, B row-major ld=ldb, C row-major ld=ldc.
// Grid: (n/BN, M/BM), 256 threads (8 warps, 2x4, 64x32 per warp).
// 3-stage cp.async pipeline, ONE __syncthreads per K-tile.
__global__ __launch_bounds__(256, 2) void gemm_tf32(
    const float* __restrict__ A, const float* __restrict__ B, float* __restrict__ C,
    int ldb, int ldc)
{
    extern __shared__ float smem[];
    const uint32_t smem_u32 = (uint32_t)__cvta_generic_to_shared(smem);

    const int tid  = threadIdx.x;
    const int lane = tid & 31;
    const int warp = tid >> 5;
    const int wm   = warp >> 2;   // 0..1
    const int wn   = warp & 3;    // 0..3
    const int m0   = blockIdx.y * BM;
    const int n0   = blockIdx.x * BN;

    float acc[4][4][4];
    #pragma unroll
    for (int i = 0; i < 4; i++)
        #pragma unroll
        for (int j = 0; j < 4; j++)
            #pragma unroll
            for (int v = 0; v < 4; v++)
                acc[i][j][v] = 0.0f;

    const float* Ag = A + (size_t)m0 * HID;
    const float* Bg = B + n0;

    // Per-thread staging indices (fixed across K-tiles)
    const int arow[4] = { (tid + 0)   >> 3, (tid + 256) >> 3, (tid + 512) >> 3, (tid + 768) >> 3 };
    const int acol    = (tid & 7) * 4;
    const int brow[4] = { (tid + 0)   >> 5, (tid + 256) >> 5, (tid + 512) >> 5, (tid + 768) >> 5 };
    const int bcol    = (tid & 31) * 4;

    #define ISSUE_TILE(KT, BUF) do {                                                   \
        const int _k0 = (KT) * BK;                                                     \
        const uint32_t _ab = smem_u32 + (uint32_t)((BUF) * STAGE) * 4;                 \
        const uint32_t _bb = _ab + (uint32_t)ASZ * 4;                                  \
        _Pragma("unroll")                                                              \
        for (int i = 0; i < 4; i++)                                                    \
            CP_ASYNC16(_ab + (uint32_t)(arow[i] * ASTR + acol) * 4,                    \
                       Ag + (size_t)arow[i] * HID + _k0 + acol);                       \
        _Pragma("unroll")                                                              \
        for (int i = 0; i < 4; i++)                                                    \
            CP_ASYNC16(_bb + (uint32_t)(brow[i] * BSTR + bcol) * 4,                    \
                       Bg + (size_t)(_k0 + brow[i]) * ldb + bcol);                     \
        asm volatile("cp.async.commit_group;");                                        \
    } while (0)

    ISSUE_TILE(0, 0);
    ISSUE_TILE(1, 1);

    const int kTiles = HID / BK;  // 32
    for (int kt = 0; kt < kTiles; kt++) {
        // Wait until tile kt complete (it is the oldest pending group).
        if (kt + 1 < kTiles) asm volatile("cp.async.wait_group 1;");
        else                 asm volatile("cp.async.wait_group 0;");
        __syncthreads();   // tile kt visible block-wide; prior iter's reads done

        // Refill the stage whose readers finished last iteration.
        if (kt + 2 < kTiles) ISSUE_TILE(kt + 2, (kt + 2) % NSTAGE);

        const float* As = smem + (kt % NSTAGE) * STAGE;
        const float* Bs = As + ASZ;
        #pragma unroll
        for (int ks = 0; ks < 4; ks++) {
            unsigned a[4][4], b[4][2];
            const int ar = wm * 64 + (lane >> 2);
            const int ac = ks * 8 + (lane & 3);
            #pragma unroll
            for (int mt = 0; mt < 4; mt++) {
                int r = ar + mt * 16;
                a[mt][0] = __float_as_uint(As[(r    ) * ASTR + ac    ]);
                a[mt][1] = __float_as_uint(As[(r + 8) * ASTR + ac    ]);
                a[mt][2] = __float_as_uint(As[(r    ) * ASTR + ac + 4]);
                a[mt][3] = __float_as_uint(As[(r + 8) * ASTR + ac + 4]);
            }
            const int bk = ks * 8 + (lane & 3);
            const int bc = wn * 32 + (lane >> 2);
            #pragma unroll
            for (int nt = 0; nt < 4; nt++) {
                b[nt][0] = __float_as_uint(Bs[(bk    ) * BSTR + bc + nt * 8]);
                b[nt][1] = __float_as_uint(Bs[(bk + 4) * BSTR + bc + nt * 8]);
            }
            #pragma unroll
            for (int mt = 0; mt < 4; mt++)
                #pragma unroll
                for (int nt = 0; nt < 4; nt++)
                    asm volatile(
                        "mma.sync.aligned.m16n8k8.row.col.f32.tf32.tf32.f32 "
                        "{%0,%1,%2,%3},{%4,%5,%6,%7},{%8,%9},{%0,%1,%2,%3};"
                        : "+f"(acc[mt][nt][0]), "+f"(acc[mt][nt][1]),
                          "+f"(acc[mt][nt][2]), "+f"(acc[mt][nt][3])
                        : "r"(a[mt][0]), "r"(a[mt][1]), "r"(a[mt][2]), "r"(a[mt][3]),
                          "r"(b[nt][0]), "r"(b[nt][1]));
        }
    }

    // Epilogue: c0,c1 at (row, 2c..2c+1); c2,c3 at (row+8, ...).
    // __stcs: U is written once and consumed once later -> keep it out of L2
    // so the B-tile working set (reused across all M-tiles) stays resident.
    const int cm = m0 + wm * 64 + (lane >> 2);
    const int cn = n0 + wn * 32 + (lane & 3) * 2;
    #pragma unroll
    for (int mt = 0; mt < 4; mt++) {
        #pragma unroll
        for (int nt = 0; nt < 4; nt++) {
            int row = cm + mt * 16;
            int col = cn + nt * 8;
            __stcs((float2*)(C + (size_t)row * ldc + col),
                   make_float2(acc[mt][nt][0], acc[mt][nt][1]));
            __stcs((float2*)(C + (size_t)(row + 8) * ldc + col),
                   make_float2(acc[mt][nt][2], acc[mt][nt][3]));
        }
    }
    #undef ISSUE_TILE
}

// Layer-1 scan + output mix: one thread per (b,h) channel, coalesced over h.
// h1 stored tf32-rounded (GEMM2 input); exact h1 at t=SEQ-1 kept separately.
__global__ __launch_bounds__(32) void scan1(const float* __restrict__ x,
                                            const float* __restrict__ bias0)
{
    const int ch = blockIdx.x * blockDim.x + threadIdx.x;  // 0..16383
    const int b = ch >> 10, h = ch & 1023;
    const float bf = bias0[h];
    const float br = bias0[HID + h];
    float c = 0.0f;
    #pragma unroll 16
    for (int t = 0; t < SEQ; t++) {
        const size_t row = (size_t)(t * BATCH + b);
        const size_t ub  = row * N0;
        float xt = __ldcs(&g_U[ub + h]);
        float f  = sigm(__ldcs(&g_U[ub + HID     + h]) + bf);
        float r  = sigm(__ldcs(&g_U[ub + 2 * HID + h]) + br);
        c = f * c + (1.0f - f) * xt;
        float xin = x[row * HID + h];
        float hv  = r * c + (1.0f - r) * xin;
        g_h1[row * HID + h] = f2tf32f(hv);
        if (t == SEQ - 1) g_hlast[ch] = hv;   // exact value for the final mix
    }
}

// r-gate pre-activation, layer 2, last timestep only:
// g_r2[b][n] = hlast[b] . W1[:, 2*HID + n]  (exact hlast, raw fp32 W1)
__global__ void rlast2(const float* __restrict__ W1)
{
    const int idx = blockIdx.x * blockDim.x + threadIdx.x;  // 16384
    const int b = idx >> 10, n = idx & 1023;
    const float* hl = g_hlast + (size_t)b * HID;
    float s = 0.0f;
    #pragma unroll 4
    for (int k = 0; k < HID; k++)
        s = fmaf(hl[k], W1[(size_t)k * N0 + 2 * HID + n], s);
    g_r2[idx] = s;
}

// Layer-2 scan (f, x~ only; ld=N1) + final output at t = SEQ-1.
__global__ __launch_bounds__(32) void scan2(const float* __restrict__ bias1,
                                            float* __restrict__ out)
{
    const int ch = blockIdx.x * blockDim.x + threadIdx.x;
    const int b = ch >> 10, h = ch & 1023;
    const float bf = bias1[h];
    const float br = bias1[HID + h];
    float c = 0.0f;
    #pragma unroll 16
    for (int t = 0; t < SEQ; t++) {
        const size_t ub = (size_t)(t * BATCH + b) * N1;
        float xt = __ldcs(&g_U[ub + h]);
        float f  = sigm(__ldcs(&g_U[ub + HID + h]) + bf);
        c = f * c + (1.0f - f) * xt;
    }
    float r  = sigm(g_r2[ch] + br);
    float hl = g_hlast[ch];               // exact h1 last step
    out[ch] = r * c + (1.0f - r) * hl;
}

extern "C" void kernel_launch(void* const* d_in, const int* in_sizes, int n_in,
                              void* d_out, int out_size)
{
    (void)in_sizes; (void)n_in; (void)out_size;
    const float* x  = (const float*)d_in[0];
    const float* W0 = (const float*)d_in[1];
    const float* b0 = (const float*)d_in[2];
    const float* W1 = (const float*)d_in[3];
    const float* b1 = (const float*)d_in[4];
    float* out = (float*)d_out;

    float *U, *h1, *xc, *W0c, *W1c;
    cudaGetSymbolAddress((void**)&U,   g_U);
    cudaGetSymbolAddress((void**)&h1,  g_h1);
    cudaGetSymbolAddress((void**)&xc,  g_xc);
    cudaGetSymbolAddress((void**)&W0c, g_W0c);
    cudaGetSymbolAddress((void**)&W1c, g_W1c);

    cudaFuncSetAttribute(gemm_tf32, cudaFuncAttributeMaxDynamicSharedMemorySize, SMEM_BYTES);

    // Pre-round inputs to tf32 (removes all CVT from the GEMM inner loop).
    tf32_round<<<1184, 256>>>((const float4*)x,  (float4*)xc,  M_TOT * HID / 4);
    tf32_round<<<592,  256>>>((const float4*)W0, (float4*)W0c, HID * N0 / 4);
    tf32_round<<<592,  256>>>((const float4*)W1, (float4*)W1c, HID * N0 / 4);

    // Layer 1: full U0 (x~, f, r needed at every t)
    gemm_tf32<<<dim3(N0 / BN, M_TOT / BM), 256, SMEM_BYTES>>>(xc, W0c, U, N0, N0);
    scan1<<<16384 / 32, 32>>>(x, b0);

    // Layer 2: only x~ and f columns over all t (N=2048), r only at last step
    gemm_tf32<<<dim3(N1 / BN, M_TOT / BM), 256, SMEM_BYTES>>>(h1, W1c, U, N0, N1);
    rlast2<<<16384 / 128, 128>>>(W1);
    scan2<<<16384 / 32, 32>>>(b1, out);
}

// round 12
// speedup vs baseline: 2.2179x; 2.2179x over previous
#include <cuda_runtime.h>
#include <cstdint>

#define SEQ    2048
#define BATCH  16
#define HID    1024
#define M_TOT  (SEQ*BATCH)   /* 32768 */
#define N0     (3*HID)       /* 3072  */
#define N1     (2*HID)       /* 2048  */

#define BM 128
#define BN 128
#define BK 32
#define ASTR (BK + 4)        /* 36  */
#define BSTR (BN + 8)        /* 136 */
#define ASZ  (BM * ASTR)     /* 4608 words */
#define BSZ  (BK * BSTR)     /* 4352 words */
#define STAGE (ASZ + BSZ)    /* 8960 words = 35840 B */
#define NSTAGE 2
#define SMEM_BYTES (NSTAGE * STAGE * 4)  /* 71680 -> 2 CTAs/SM */

/* chunked scan geometry */
#define NCHK 32
#define CLEN (SEQ/NCHK)      /* 64 */
#define NCH_TOT (BATCH*HID)  /* 16384 channels */

// Scratch (device globals: allocation APIs are forbidden)
__device__ float g_U    [(size_t)M_TOT * N0];   // U0 (ld=3072), then U1 (ld=2048)
__device__ float g_h1   [(size_t)M_TOT * HID];  // layer-1 output (tf32-rounded at store)
__device__ float g_hlast[NCH_TOT];              // exact h1 at t=SEQ-1
__device__ float g_xc   [(size_t)M_TOT * HID];  // x, tf32-rounded
__device__ float g_W0c  [(size_t)HID * N0];     // W0, tf32-rounded
__device__ float g_W1c  [(size_t)HID * N0];     // W1, tf32-rounded
__device__ float g_r2   [NCH_TOT];              // last-step r pre-activation, layer 2
__device__ float g_P    [NCHK * NCH_TOT];       // per-chunk decay product
__device__ float g_cend [NCHK * NCH_TOT];       // per-chunk zero-state end value
__device__ float g_cin  [NCHK * NCH_TOT];       // per-chunk entry state

__device__ __forceinline__ float f2tf32f(float f) {
    unsigned u;
    asm("cvt.rna.tf32.f32 %0, %1;" : "=r"(u) : "f"(f));
    return __uint_as_float(u);
}

__device__ __forceinline__ float sigm(float z) {
    return 1.0f / (1.0f + __expf(-z));
}

#define CP_ASYNC16(dst_u32, src_ptr) \
    asm volatile("cp.async.ca.shared.global [%0], [%1], 16;" :: "r"(dst_u32), "l"(src_ptr))

// Round an fp32 array to tf32 (bits in fp32 container). Pure streaming.
__global__ void tf32_round(const float4* __restrict__ src, float4* __restrict__ dst, int n4)
{
    for (int i = blockIdx.x * blockDim.x + threadIdx.x; i < n4; i += gridDim.x * blockDim.x) {
        float4 v = __ldcs(&src[i]);
        v.x = f2tf32f(v.x); v.y = f2tf32f(v.y);
        v.z = f2tf32f(v.z); v.w = f2tf32f(v.w);
        __stcs(&dst[i], v);
    }
}

// C[M x n] = A[M x 1024] @ B[1024 x n]; inputs pre-rounded to tf32.
// 2-stage cp.async pipeline, issue-after-read (WAR-safe), 2 CTAs/SM.
__global__ __launch_bounds__(256, 2) void gemm_tf32(
    const float* __restrict__ A, const float* __restrict__ B, float* __restrict__ C,
    int ldb, int ldc)
{
    extern __shared__ float smem[];
    const uint32_t smem_u32 = (uint32_t)__cvta_generic_to_shared(smem);

    const int tid  = threadIdx.x;
    const int lane = tid & 31;
    const int warp = tid >> 5;
    const int wm   = warp >> 2;   // 0..1
    const int wn   = warp & 3;    // 0..3
    const int m0   = blockIdx.y * BM;
    const int n0   = blockIdx.x * BN;

    float acc[4][4][4];
    #pragma unroll
    for (int i = 0; i < 4; i++)
        #pragma unroll
        for (int j = 0; j < 4; j++)
            #pragma unroll
            for (int v = 0; v < 4; v++)
                acc[i][j][v] = 0.0f;

    const float* Ag = A + (size_t)m0 * HID;
    const float* Bg = B + n0;

    const int arow[4] = { (tid + 0)   >> 3, (tid + 256) >> 3, (tid + 512) >> 3, (tid + 768) >> 3 };
    const int acol    = (tid & 7) * 4;
    const int brow[4] = { (tid + 0)   >> 5, (tid + 256) >> 5, (tid + 512) >> 5, (tid + 768) >> 5 };
    const int bcol    = (tid & 31) * 4;

    #define ISSUE_TILE(KT, BUF) do {                                                   \
        const int _k0 = (KT) * BK;                                                     \
        const uint32_t _ab = smem_u32 + (uint32_t)((BUF) * STAGE) * 4;                 \
        const uint32_t _bb = _ab + (uint32_t)ASZ * 4;                                  \
        _Pragma("unroll")                                                              \
        for (int i = 0; i < 4; i++)                                                    \
            CP_ASYNC16(_ab + (uint32_t)(arow[i] * ASTR + acol) * 4,                    \
                       Ag + (size_t)arow[i] * HID + _k0 + acol);                       \
        _Pragma("unroll")                                                              \
        for (int i = 0; i < 4; i++)                                                    \
            CP_ASYNC16(_bb + (uint32_t)(brow[i] * BSTR + bcol) * 4,                    \
                       Bg + (size_t)(_k0 + brow[i]) * ldb + bcol);                     \
        asm volatile("cp.async.commit_group;");                                        \
    } while (0)

    ISSUE_TILE(0, 0);
    ISSUE_TILE(1, 1);

    const int kTiles = HID / BK;  // 32
    for (int kt = 0; kt < kTiles; kt++) {
        if (kt + 1 < kTiles) asm volatile("cp.async.wait_group 1;");
        else                 asm volatile("cp.async.wait_group 0;");
        __syncthreads();   // tile kt visible block-wide

        const float* As = smem + (kt & 1) * STAGE;
        const float* Bs = As + ASZ;
        #pragma unroll
        for (int ks = 0; ks < 4; ks++) {
            unsigned a[4][4], b[4][2];
            const int ar = wm * 64 + (lane >> 2);
            const int ac = ks * 8 + (lane & 3);
            #pragma unroll
            for (int mt = 0; mt < 4; mt++) {
                int r = ar + mt * 16;
                a[mt][0] = __float_as_uint(As[(r    ) * ASTR + ac    ]);
                a[mt][1] = __float_as_uint(As[(r + 8) * ASTR + ac    ]);
                a[mt][2] = __float_as_uint(As[(r    ) * ASTR + ac + 4]);
                a[mt][3] = __float_as_uint(As[(r + 8) * ASTR + ac + 4]);
            }
            const int bk = ks * 8 + (lane & 3);
            const int bc = wn * 32 + (lane >> 2);
            #pragma unroll
            for (int nt = 0; nt < 4; nt++) {
                b[nt][0] = __float_as_uint(Bs[(bk    ) * BSTR + bc + nt * 8]);
                b[nt][1] = __float_as_uint(Bs[(bk + 4) * BSTR + bc + nt * 8]);
            }
            #pragma unroll
            for (int mt = 0; mt < 4; mt++)
                #pragma unroll
                for (int nt = 0; nt < 4; nt++)
                    asm volatile(
                        "mma.sync.aligned.m16n8k8.row.col.f32.tf32.tf32.f32 "
                        "{%0,%1,%2,%3},{%4,%5,%6,%7},{%8,%9},{%0,%1,%2,%3};"
                        : "+f"(acc[mt][nt][0]), "+f"(acc[mt][nt][1]),
                          "+f"(acc[mt][nt][2]), "+f"(acc[mt][nt][3])
                        : "r"(a[mt][0]), "r"(a[mt][1]), "r"(a[mt][2]), "r"(a[mt][3]),
                          "r"(b[nt][0]), "r"(b[nt][1]));
        }
        __syncthreads();   // all warps done reading stage (kt&1)
        if (kt + 2 < kTiles) ISSUE_TILE(kt + 2, kt & 1);  // refill freed stage
    }

    const int cm = m0 + wm * 64 + (lane >> 2);
    const int cn = n0 + wn * 32 + (lane & 3) * 2;
    #pragma unroll
    for (int mt = 0; mt < 4; mt++) {
        #pragma unroll
        for (int nt = 0; nt < 4; nt++) {
            int row = cm + mt * 16;
            int col = cn + nt * 8;
            __stcs((float2*)(C + (size_t)row * ldc + col),
                   make_float2(acc[mt][nt][0], acc[mt][nt][1]));
            __stcs((float2*)(C + (size_t)(row + 8) * ldc + col),
                   make_float2(acc[mt][nt][2], acc[mt][nt][3]));
        }
    }
    #undef ISSUE_TILE
}

/* -------- chunked scans: 32 chunks x 64 steps, 524288-way parallel -------- */

// Pass A (either layer): per (chunk, channel) compute decay product P and
// zero-state end value c_end over the chunk. ldU selects U0 (3072) or U1 (2048).
__global__ __launch_bounds__(256) void scan_partial(const float* __restrict__ bias,
                                                    int ldU)
{
    const int idx = blockIdx.x * blockDim.x + threadIdx.x;  // 0..524287
    const int ch = idx & (NCH_TOT - 1), chunk = idx >> 14;
    const int b = ch >> 10, h = ch & 1023;
    const float bf = bias[h];
    const int t0 = chunk * CLEN;
    float c = 0.0f, P = 1.0f;
    #pragma unroll 8
    for (int i = 0; i < CLEN; i++) {
        const size_t ub = (size_t)((t0 + i) * BATCH + b) * ldU;
        float xt = __ldcs(&g_U[ub + h]);
        float f  = sigm(__ldcs(&g_U[ub + HID + h]) + bf);
        c = f * c + (1.0f - f) * xt;
        P *= f;
    }
    g_P[idx] = P;
    g_cend[idx] = c;
}

// Combine for layer 1: record entry state per chunk.
__global__ void scan_combine_states()
{
    const int ch = blockIdx.x * blockDim.x + threadIdx.x;  // 16384
    float c = 0.0f;
    #pragma unroll
    for (int k = 0; k < NCHK; k++) {
        g_cin[k * NCH_TOT + ch] = c;
        c = g_P[k * NCH_TOT + ch] * c + g_cend[k * NCH_TOT + ch];
    }
}

// Pass C, layer 1 only: replay each chunk from its entry state, emit h1 (+hlast).
__global__ __launch_bounds__(256) void scan1_final(const float* __restrict__ x,
                                                   const float* __restrict__ bias0)
{
    const int idx = blockIdx.x * blockDim.x + threadIdx.x;
    const int ch = idx & (NCH_TOT - 1), chunk = idx >> 14;
    const int b = ch >> 10, h = ch & 1023;
    const float bf = bias0[h];
    const float br = bias0[HID + h];
    const int t0 = chunk * CLEN;
    float c = g_cin[chunk * NCH_TOT + ch];
    #pragma unroll 8
    for (int i = 0; i < CLEN; i++) {
        const size_t row = (size_t)((t0 + i) * BATCH + b);
        const size_t ub  = row * N0;
        float xt = __ldcs(&g_U[ub + h]);
        float f  = sigm(__ldcs(&g_U[ub + HID     + h]) + bf);
        float r  = sigm(__ldcs(&g_U[ub + 2 * HID + h]) + br);
        c = f * c + (1.0f - f) * xt;
        float xin = __ldcs(&x[row * HID + h]);
        float hv  = r * c + (1.0f - r) * xin;
        g_h1[row * HID + h] = f2tf32f(hv);
        if (chunk == NCHK - 1 && i == CLEN - 1) g_hlast[ch] = hv;  // exact
    }
}

// r-gate pre-activation, layer 2, last timestep only.
__global__ void rlast2(const float* __restrict__ W1)
{
    const int idx = blockIdx.x * blockDim.x + threadIdx.x;  // 16384
    const int b = idx >> 10, n = idx & 1023;
    const float* hl = g_hlast + (size_t)b * HID;
    float s = 0.0f;
    #pragma unroll 4
    for (int k = 0; k < HID; k++)
        s = fmaf(hl[k], W1[(size_t)k * N0 + 2 * HID + n], s);
    g_r2[idx] = s;
}

// Layer-2 finish: chain chunk summaries to the final c, mix with r and hlast.
__global__ void scan2_finish(const float* __restrict__ bias1, float* __restrict__ out)
{
    const int ch = blockIdx.x * blockDim.x + threadIdx.x;  // 16384
    const int h = ch & 1023;
    float c = 0.0f;
    #pragma unroll
    for (int k = 0; k < NCHK; k++)
        c = g_P[k * NCH_TOT + ch] * c + g_cend[k * NCH_TOT + ch];
    float r = sigm(g_r2[ch] + bias1[HID + h]);
    out[ch] = r * c + (1.0f - r) * g_hlast[ch];
}

extern "C" void kernel_launch(void* const* d_in, const int* in_sizes, int n_in,
                              void* d_out, int out_size)
{
    (void)in_sizes; (void)n_in; (void)out_size;
    const float* x  = (const float*)d_in[0];
    const float* W0 = (const float*)d_in[1];
    const float* b0 = (const float*)d_in[2];
    const float* W1 = (const float*)d_in[3];
    const float* b1 = (const float*)d_in[4];
    float* out = (float*)d_out;

    float *U, *h1, *xc, *W0c, *W1c;
    cudaGetSymbolAddress((void**)&U,   g_U);
    cudaGetSymbolAddress((void**)&h1,  g_h1);
    cudaGetSymbolAddress((void**)&xc,  g_xc);
    cudaGetSymbolAddress((void**)&W0c, g_W0c);
    cudaGetSymbolAddress((void**)&W1c, g_W1c);

    cudaFuncSetAttribute(gemm_tf32, cudaFuncAttributeMaxDynamicSharedMemorySize, SMEM_BYTES);

    // Pre-round inputs to tf32 (keeps CVT out of the GEMM inner loop).
    tf32_round<<<1184, 256>>>((const float4*)x,  (float4*)xc,  M_TOT * HID / 4);
    tf32_round<<<592,  256>>>((const float4*)W0, (float4*)W0c, HID * N0 / 4);
    tf32_round<<<592,  256>>>((const float4*)W1, (float4*)W1c, HID * N0 / 4);

    // Layer 1: U0 = x @ W0 (full 3072 cols), then chunked scan.
    gemm_tf32<<<dim3(N0 / BN, M_TOT / BM), 256, SMEM_BYTES>>>(xc, W0c, U, N0, N0);
    scan_partial<<<NCHK * NCH_TOT / 256, 256>>>(b0, N0);
    scan_combine_states<<<NCH_TOT / 256, 256>>>();
    scan1_final<<<NCHK * NCH_TOT / 256, 256>>>(x, b0);

    // Layer 2: U1 = h1 @ W1[:, :2048]; r-gate only at t=T-1.
    gemm_tf32<<<dim3(N1 / BN, M_TOT / BM), 256, SMEM_BYTES>>>(h1, W1c, U, N0, N1);
    scan_partial<<<NCHK * NCH_TOT / 256, 256>>>(b1, N1);
    rlast2<<<NCH_TOT / 128, 128>>>(W1);
    scan2_finish<<<NCH_TOT / 256, 256>>>(b1, out);
}

// round 15
// speedup vs baseline: 2.2759x; 1.0261x over previous
#include <cuda_runtime.h>
#include <cstdint>

#define SEQ    2048
#define BATCH  16
#define HID    1024
#define M_TOT  (SEQ*BATCH)   /* 32768 */
#define N0     (3*HID)       /* 3072  */
#define N1     (2*HID)       /* 2048  */

#define BM 128
#define BN 256
#define BK 32
#define ASTR (BK + 4)        /* 36  */
#define BSTR (BN + 8)        /* 264 */
#define ASZ  (BM * ASTR)     /* 4608 words */
#define BSZ  (BK * BSTR)     /* 8448 words */
#define STAGE (ASZ + BSZ)    /* 13056 words = 52224 B */
#define NSTAGE 3
#define SMEM_BYTES (NSTAGE * STAGE * 4)  /* 156672 B, 1 CTA/SM */

/* chunked scan geometry */
#define NCHK 32
#define CLEN (SEQ/NCHK)      /* 64 */
#define NCH_TOT (BATCH*HID)  /* 16384 channels */

// Scratch (device globals: allocation APIs are forbidden)
__device__ float g_U    [(size_t)M_TOT * N0];   // U0 (ld=3072), then U1 (ld=2048)
__device__ float g_h1   [(size_t)M_TOT * HID];  // layer-1 output (tf32-rounded at store)
__device__ float g_hlast[NCH_TOT];              // exact h1 at t=SEQ-1
__device__ float g_xc   [(size_t)M_TOT * HID];  // x, tf32-rounded
__device__ float g_W0c  [(size_t)HID * N0];     // W0, tf32-rounded
__device__ float g_W1c  [(size_t)HID * N0];     // W1, tf32-rounded
__device__ float g_r2   [NCH_TOT];              // last-step r pre-activation, layer 2
__device__ float g_P    [NCHK * NCH_TOT];       // per-chunk decay product
__device__ float g_cend [NCHK * NCH_TOT];       // per-chunk zero-state end value
__device__ float g_cin  [NCHK * NCH_TOT];       // per-chunk entry state

__device__ __forceinline__ float f2tf32f(float f) {
    unsigned u;
    asm("cvt.rna.tf32.f32 %0, %1;" : "=r"(u) : "f"(f));
    return __uint_as_float(u);
}

__device__ __forceinline__ float sigm(float z) {
    return 1.0f / (1.0f + __expf(-z));
}

#define CP_ASYNC16(dst_u32, src_ptr) \
    asm volatile("cp.async.ca.shared.global [%0], [%1], 16;" :: "r"(dst_u32), "l"(src_ptr))

// Round an fp32 array to tf32 (bits in fp32 container). Pure streaming.
__global__ void tf32_round(const float4* __restrict__ src, float4* __restrict__ dst, int n4)
{
    for (int i = blockIdx.x * blockDim.x + threadIdx.x; i < n4; i += gridDim.x * blockDim.x) {
        float4 v = __ldcs(&src[i]);
        v.x = f2tf32f(v.x); v.y = f2tf32f(v.y);
        v.z = f2tf32f(v.z); v.w = f2tf32f(v.w);
        __stcs(&dst[i], v);
    }
}

// C[M x n] = A[M x 1024] @ B[1024 x n]; inputs pre-rounded to tf32.
// CTA 128x256, warp tile 64x64 (8 warps, 2x4), LDS:HMMA = 1:1.
// 3-stage cp.async pipeline, ONE __syncthreads per K-tile.
__global__ __launch_bounds__(256, 1) void gemm_tf32(
    const float* __restrict__ A, const float* __restrict__ B, float* __restrict__ C,
    int ldb, int ldc)
{
    extern __shared__ float smem[];
    const uint32_t smem_u32 = (uint32_t)__cvta_generic_to_shared(smem);

    const int tid  = threadIdx.x;
    const int lane = tid & 31;
    const int warp = tid >> 5;
    const int wm   = warp >> 2;   // 0..1 (rows of 64)
    const int wn   = warp & 3;    // 0..3 (cols of 64)
    const int m0   = blockIdx.y * BM;
    const int n0   = blockIdx.x * BN;

    float acc[4][8][4];
    #pragma unroll
    for (int i = 0; i < 4; i++)
        #pragma unroll
        for (int j = 0; j < 8; j++)
            #pragma unroll
            for (int v = 0; v < 4; v++)
                acc[i][j][v] = 0.0f;

    const float* Ag = A + (size_t)m0 * HID;
    const float* Bg = B + n0;

    // Staging indices: A = 128x32 (1024 chunks of 16B), B = 32x256 (2048 chunks)
    const int arow[4] = { (tid + 0)   >> 3, (tid + 256) >> 3, (tid + 512) >> 3, (tid + 768) >> 3 };
    const int acol    = (tid & 7) * 4;

    #define ISSUE_TILE(KT, BUF) do {                                                   \
        const int _k0 = (KT) * BK;                                                     \
        const uint32_t _ab = smem_u32 + (uint32_t)((BUF) * STAGE) * 4;                 \
        const uint32_t _bb = _ab + (uint32_t)ASZ * 4;                                  \
        _Pragma("unroll")                                                              \
        for (int i = 0; i < 4; i++)                                                    \
            CP_ASYNC16(_ab + (uint32_t)(arow[i] * ASTR + acol) * 4,                    \
                       Ag + (size_t)arow[i] * HID + _k0 + acol);                       \
        _Pragma("unroll")                                                              \
        for (int i = 0; i < 8; i++) {                                                  \
            const int _id = tid + i * 256;                                             \
            const int _br = _id >> 6;                                                  \
            const int _bc = (_id & 63) * 4;                                            \
            CP_ASYNC16(_bb + (uint32_t)(_br * BSTR + _bc) * 4,                         \
                       Bg + (size_t)(_k0 + _br) * ldb + _bc);                          \
        }                                                                              \
        asm volatile("cp.async.commit_group;");                                        \
    } while (0)

    ISSUE_TILE(0, 0);
    ISSUE_TILE(1, 1);

    const int kTiles = HID / BK;  // 32
    for (int kt = 0; kt < kTiles; kt++) {
        if (kt + 1 < kTiles) asm volatile("cp.async.wait_group 1;");
        else                 asm volatile("cp.async.wait_group 0;");
        __syncthreads();   // tile kt visible; all warps done reading tile kt-1

        if (kt + 2 < kTiles) ISSUE_TILE(kt + 2, (kt + 2) % NSTAGE);  // refills (kt-1)%3

        const float* As = smem + (kt % NSTAGE) * STAGE;
        const float* Bs = As + ASZ;
        #pragma unroll
        for (int ks = 0; ks < 4; ks++) {
            unsigned a[4][4], b[8][2];
            const int ar = wm * 64 + (lane >> 2);
            const int ac = ks * 8 + (lane & 3);
            #pragma unroll
            for (int mt = 0; mt < 4; mt++) {
                int r = ar + mt * 16;
                a[mt][0] = __float_as_uint(As[(r    ) * ASTR + ac    ]);
                a[mt][1] = __float_as_uint(As[(r + 8) * ASTR + ac    ]);
                a[mt][2] = __float_as_uint(As[(r    ) * ASTR + ac + 4]);
                a[mt][3] = __float_as_uint(As[(r + 8) * ASTR + ac + 4]);
            }
            const int bk = ks * 8 + (lane & 3);
            const int bc = wn * 64 + (lane >> 2);
            #pragma unroll
            for (int nt = 0; nt < 8; nt++) {
                b[nt][0] = __float_as_uint(Bs[(bk    ) * BSTR + bc + nt * 8]);
                b[nt][1] = __float_as_uint(Bs[(bk + 4) * BSTR + bc + nt * 8]);
            }
            #pragma unroll
            for (int mt = 0; mt < 4; mt++)
                #pragma unroll
                for (int nt = 0; nt < 8; nt++)
                    asm volatile(
                        "mma.sync.aligned.m16n8k8.row.col.f32.tf32.tf32.f32 "
                        "{%0,%1,%2,%3},{%4,%5,%6,%7},{%8,%9},{%0,%1,%2,%3};"
                        : "+f"(acc[mt][nt][0]), "+f"(acc[mt][nt][1]),
                          "+f"(acc[mt][nt][2]), "+f"(acc[mt][nt][3])
                        : "r"(a[mt][0]), "r"(a[mt][1]), "r"(a[mt][2]), "r"(a[mt][3]),
                          "r"(b[nt][0]), "r"(b[nt][1]));
        }
    }

    const int cm = m0 + wm * 64 + (lane >> 2);
    const int cn = n0 + wn * 64 + (lane & 3) * 2;
    #pragma unroll
    for (int mt = 0; mt < 4; mt++) {
        #pragma unroll
        for (int nt = 0; nt < 8; nt++) {
            int row = cm + mt * 16;
            int col = cn + nt * 8;
            __stcs((float2*)(C + (size_t)row * ldc + col),
                   make_float2(acc[mt][nt][0], acc[mt][nt][1]));
            __stcs((float2*)(C + (size_t)(row + 8) * ldc + col),
                   make_float2(acc[mt][nt][2], acc[mt][nt][3]));
        }
    }
    #undef ISSUE_TILE
}

/* -------- chunked scans: 32 chunks x 64 steps, 524288-way parallel -------- */

__global__ __launch_bounds__(256) void scan_partial(const float* __restrict__ bias,
                                                    int ldU)
{
    const int idx = blockIdx.x * blockDim.x + threadIdx.x;  // 0..524287
    const int ch = idx & (NCH_TOT - 1), chunk = idx >> 14;
    const int b = ch >> 10, h = ch & 1023;
    const float bf = bias[h];
    const int t0 = chunk * CLEN;
    float c = 0.0f, P = 1.0f;
    #pragma unroll 8
    for (int i = 0; i < CLEN; i++) {
        const size_t ub = (size_t)((t0 + i) * BATCH + b) * ldU;
        float xt = __ldcs(&g_U[ub + h]);
        float f  = sigm(__ldcs(&g_U[ub + HID + h]) + bf);
        c = f * c + (1.0f - f) * xt;
        P *= f;
    }
    g_P[idx] = P;
    g_cend[idx] = c;
}

__global__ void scan_combine_states()
{
    const int ch = blockIdx.x * blockDim.x + threadIdx.x;  // 16384
    float c = 0.0f;
    #pragma unroll
    for (int k = 0; k < NCHK; k++) {
        g_cin[k * NCH_TOT + ch] = c;
        c = g_P[k * NCH_TOT + ch] * c + g_cend[k * NCH_TOT + ch];
    }
}

__global__ __launch_bounds__(256) void scan1_final(const float* __restrict__ x,
                                                   const float* __restrict__ bias0)
{
    const int idx = blockIdx.x * blockDim.x + threadIdx.x;
    const int ch = idx & (NCH_TOT - 1), chunk = idx >> 14;
    const int b = ch >> 10, h = ch & 1023;
    const float bf = bias0[h];
    const float br = bias0[HID + h];
    const int t0 = chunk * CLEN;
    float c = g_cin[chunk * NCH_TOT + ch];
    #pragma unroll 8
    for (int i = 0; i < CLEN; i++) {
        const size_t row = (size_t)((t0 + i) * BATCH + b);
        const size_t ub  = row * N0;
        float xt = __ldcs(&g_U[ub + h]);
        float f  = sigm(__ldcs(&g_U[ub + HID     + h]) + bf);
        float r  = sigm(__ldcs(&g_U[ub + 2 * HID + h]) + br);
        c = f * c + (1.0f - f) * xt;
        float xin = __ldcs(&x[row * HID + h]);
        float hv  = r * c + (1.0f - r) * xin;
        g_h1[row * HID + h] = f2tf32f(hv);
        if (chunk == NCHK - 1 && i == CLEN - 1) g_hlast[ch] = hv;  // exact
    }
}

__global__ void rlast2(const float* __restrict__ W1)
{
    const int idx = blockIdx.x * blockDim.x + threadIdx.x;  // 16384
    const int b = idx >> 10, n = idx & 1023;
    const float* hl = g_hlast + (size_t)b * HID;
    float s = 0.0f;
    #pragma unroll 4
    for (int k = 0; k < HID; k++)
        s = fmaf(hl[k], W1[(size_t)k * N0 + 2 * HID + n], s);
    g_r2[idx] = s;
}

__global__ void scan2_finish(const float* __restrict__ bias1, float* __restrict__ out)
{
    const int ch = blockIdx.x * blockDim.x + threadIdx.x;  // 16384
    const int h = ch & 1023;
    float c = 0.0f;
    #pragma unroll
    for (int k = 0; k < NCHK; k++)
        c = g_P[k * NCH_TOT + ch] * c + g_cend[k * NCH_TOT + ch];
    float r = sigm(g_r2[ch] + bias1[HID + h]);
    out[ch] = r * c + (1.0f - r) * g_hlast[ch];
}

extern "C" void kernel_launch(void* const* d_in, const int* in_sizes, int n_in,
                              void* d_out, int out_size)
{
    (void)in_sizes; (void)n_in; (void)out_size;
    const float* x  = (const float*)d_in[0];
    const float* W0 = (const float*)d_in[1];
    const float* b0 = (const float*)d_in[2];
    const float* W1 = (const float*)d_in[3];
    const float* b1 = (const float*)d_in[4];
    float* out = (float*)d_out;

    float *U, *h1, *xc, *W0c, *W1c;
    cudaGetSymbolAddress((void**)&U,   g_U);
    cudaGetSymbolAddress((void**)&h1,  g_h1);
    cudaGetSymbolAddress((void**)&xc,  g_xc);
    cudaGetSymbolAddress((void**)&W0c, g_W0c);
    cudaGetSymbolAddress((void**)&W1c, g_W1c);

    cudaFuncSetAttribute(gemm_tf32, cudaFuncAttributeMaxDynamicSharedMemorySize, SMEM_BYTES);

    // Pre-round inputs to tf32 (keeps CVT out of the GEMM inner loop).
    tf32_round<<<1184, 256>>>((const float4*)x,  (float4*)xc,  M_TOT * HID / 4);
    tf32_round<<<592,  256>>>((const float4*)W0, (float4*)W0c, HID * N0 / 4);
    tf32_round<<<592,  256>>>((const float4*)W1, (float4*)W1c, HID * N0 / 4);

    // Layer 1: U0 = x @ W0 (full 3072 cols), then chunked scan.
    gemm_tf32<<<dim3(N0 / BN, M_TOT / BM), 256, SMEM_BYTES>>>(xc, W0c, U, N0, N0);
    scan_partial<<<NCHK * NCH_TOT / 256, 256>>>(b0, N0);
    scan_combine_states<<<NCH_TOT / 256, 256>>>();
    scan1_final<<<NCHK * NCH_TOT / 256, 256>>>(x, b0);

    // Layer 2: U1 = h1 @ W1[:, :2048]; r-gate only at t=T-1.
    gemm_tf32<<<dim3(N1 / BN, M_TOT / BM), 256, SMEM_BYTES>>>(h1, W1c, U, N0, N1);
    scan_partial<<<NCHK * NCH_TOT / 256, 256>>>(b1, N1);
    rlast2<<<NCH_TOT / 128, 128>>>(W1);
    scan2_finish<<<NCH_TOT / 256, 256>>>(b1, out);
}